// round 2
// baseline (speedup 1.0000x reference)
#include <cuda_runtime.h>

#define Bdim 4
#define Sdim 4096
#define Hdim 1024
#define Mtot (Bdim * Sdim)

// Scratch (device globals: allocation-free per harness rules)
__device__ float g_q[(size_t)Bdim * Sdim * Hdim];
__device__ float g_k[(size_t)Bdim * Sdim * Hdim];
__device__ float g_v[(size_t)Bdim * Sdim * Hdim];
__device__ float g_e[(size_t)Bdim * Sdim * Sdim];

// ---- packed f32x2 helpers (sm_103a: doubles fp32 FMA throughput vs FFMA-3reg) ----
__device__ __forceinline__ unsigned long long pack2(float lo, float hi) {
    unsigned long long r;
    asm("mov.b64 %0, {%1, %2};" : "=l"(r)
        : "r"(__float_as_uint(lo)), "r"(__float_as_uint(hi)));
    return r;
}
__device__ __forceinline__ void unpack2(unsigned long long v, float& lo, float& hi) {
    unsigned int a, b;
    asm("mov.b64 {%0, %1}, %2;" : "=r"(a), "=r"(b) : "l"(v));
    lo = __uint_as_float(a); hi = __uint_as_float(b);
}
__device__ __forceinline__ unsigned long long fma2(unsigned long long a,
                                                   unsigned long long b,
                                                   unsigned long long c) {
    unsigned long long d;
    asm("fma.rn.f32x2 %0, %1, %2, %3;" : "=l"(d) : "l"(a), "l"(b), "l"(c));
    return d;
}

// ---- generic tiled GEMM: C = scale * (A @ B[^T]) + bias ----
// A: M x K row-major.  NN: B is K x N row-major.  NT: B is N x K row-major (B^T used).
// Per-blockIdx.z batch strides sA/sB/sC. BM=BN=128, BK=16, 256 threads, 8x8/thread.
template <bool NT, bool HASBIAS>
__global__ __launch_bounds__(256, 2)
void gemm_kernel(const float* __restrict__ A, const float* __restrict__ Bm,
                 const float* __restrict__ bias, float* __restrict__ C,
                 int M, int N, int K,
                 long long sA, long long sB, long long sC, float scale)
{
    const int BM = 128, BN = 128, BK = 16;
    __shared__ float As[BK][BM];
    __shared__ float Bs[BK][BN];

    A  += (size_t)blockIdx.z * sA;
    Bm += (size_t)blockIdx.z * sB;
    C  += (size_t)blockIdx.z * sC;

    const int t  = threadIdx.x;
    const int tx = t & 15;        // 0..15 -> N direction (8 cols each)
    const int ty = t >> 4;        // 0..15 -> M direction (8 rows each)
    const int m0 = blockIdx.y * BM;
    const int n0 = blockIdx.x * BN;

    // A-tile (and NT B-tile) load indices: float4 along K, store transposed
    const int arow = t >> 2;          // 0..63
    const int acol = (t & 3) * 4;     // 0,4,8,12
    // NN B-tile load indices: float4 along N
    const int brow = t >> 5;          // 0..7
    const int bcol = (t & 31) * 4;    // 0..124

    unsigned long long acc[8][4];
#pragma unroll
    for (int i = 0; i < 8; i++)
#pragma unroll
        for (int j = 0; j < 4; j++) acc[i][j] = 0ULL;

    for (int k0 = 0; k0 < K; k0 += BK) {
#pragma unroll
        for (int p = 0; p < 2; p++) {
            int r = arow + p * 64;
            float4 a = *(const float4*)&A[(size_t)(m0 + r) * K + k0 + acol];
            As[acol + 0][r] = a.x; As[acol + 1][r] = a.y;
            As[acol + 2][r] = a.z; As[acol + 3][r] = a.w;
        }
        if (NT) {
#pragma unroll
            for (int p = 0; p < 2; p++) {
                int r = arow + p * 64;
                float4 b = *(const float4*)&Bm[(size_t)(n0 + r) * K + k0 + acol];
                Bs[acol + 0][r] = b.x; Bs[acol + 1][r] = b.y;
                Bs[acol + 2][r] = b.z; Bs[acol + 3][r] = b.w;
            }
        } else {
#pragma unroll
            for (int p = 0; p < 2; p++) {
                int r = brow + p * 8;
                *(float4*)&Bs[r][bcol] =
                    *(const float4*)&Bm[(size_t)(k0 + r) * N + n0 + bcol];
            }
        }
        __syncthreads();

#pragma unroll
        for (int kk = 0; kk < BK; kk++) {
            float4 a0 = *(const float4*)&As[kk][ty * 8];
            float4 a1 = *(const float4*)&As[kk][ty * 8 + 4];
            const unsigned long long* b64 =
                (const unsigned long long*)&Bs[kk][tx * 8];
            unsigned long long b0 = b64[0], b1 = b64[1], b2 = b64[2], b3 = b64[3];
            float am[8] = {a0.x, a0.y, a0.z, a0.w, a1.x, a1.y, a1.z, a1.w};
#pragma unroll
            for (int i = 0; i < 8; i++) {
                unsigned long long ap = pack2(am[i], am[i]);
                acc[i][0] = fma2(ap, b0, acc[i][0]);
                acc[i][1] = fma2(ap, b1, acc[i][1]);
                acc[i][2] = fma2(ap, b2, acc[i][2]);
                acc[i][3] = fma2(ap, b3, acc[i][3]);
            }
        }
        __syncthreads();
    }

    float bv[8];
#pragma unroll
    for (int j = 0; j < 8; j++) bv[j] = HASBIAS ? bias[n0 + tx * 8 + j] : 0.0f;

#pragma unroll
    for (int i = 0; i < 8; i++) {
        float o[8];
#pragma unroll
        for (int j = 0; j < 4; j++) {
            float lo, hi;
            unpack2(acc[i][j], lo, hi);
            o[2 * j]     = lo * scale + bv[2 * j];
            o[2 * j + 1] = hi * scale + bv[2 * j + 1];
        }
        float* crow = &C[(size_t)(m0 + ty * 8 + i) * N + n0 + tx * 8];
        *(float4*)(crow)     = make_float4(o[0], o[1], o[2], o[3]);
        *(float4*)(crow + 4) = make_float4(o[4], o[5], o[6], o[7]);
    }
}

// ---- row softmax over S=4096 elements, one block/row, 256 threads ----
__global__ void softmax_kernel(float* __restrict__ e)
{
    const int row = blockIdx.x;
    float4* p = (float4*)(e + (size_t)row * Sdim);
    const int t = threadIdx.x;

    float4 v[4];
    float mx = -1e30f;
#pragma unroll
    for (int c = 0; c < 4; c++) {
        v[c] = p[t + c * 256];
        mx = fmaxf(mx, fmaxf(fmaxf(v[c].x, v[c].y), fmaxf(v[c].z, v[c].w)));
    }

    __shared__ float red[256];
    red[t] = mx;
    __syncthreads();
    for (int s = 128; s > 0; s >>= 1) {
        if (t < s) red[t] = fmaxf(red[t], red[t + s]);
        __syncthreads();
    }
    mx = red[0];
    __syncthreads();

    float sum = 0.0f;
#pragma unroll
    for (int c = 0; c < 4; c++) {
        v[c].x = __expf(v[c].x - mx);
        v[c].y = __expf(v[c].y - mx);
        v[c].z = __expf(v[c].z - mx);
        v[c].w = __expf(v[c].w - mx);
        sum += v[c].x + v[c].y + v[c].z + v[c].w;
    }
    red[t] = sum;
    __syncthreads();
    for (int s = 128; s > 0; s >>= 1) {
        if (t < s) red[t] += red[t + s];
        __syncthreads();
    }
    float inv = 1.0f / red[0];
#pragma unroll
    for (int c = 0; c < 4; c++) {
        v[c].x *= inv; v[c].y *= inv; v[c].z *= inv; v[c].w *= inv;
        p[t + c * 256] = v[c];
    }
}

extern "C" void kernel_launch(void* const* d_in, const int* in_sizes, int n_in,
                              void* d_out, int out_size)
{
    const float* x  = (const float*)d_in[0];
    const float* Wq = (const float*)d_in[1];
    const float* bq = (const float*)d_in[2];
    const float* Wk = (const float*)d_in[3];
    const float* bk = (const float*)d_in[4];
    const float* Wv = (const float*)d_in[5];
    const float* bv = (const float*)d_in[6];
    float* out = (float*)d_out;

    float *q, *k, *v, *e;
    cudaGetSymbolAddress((void**)&q, g_q);
    cudaGetSymbolAddress((void**)&k, g_k);
    cudaGetSymbolAddress((void**)&v, g_v);
    cudaGetSymbolAddress((void**)&e, g_e);

    dim3 blk(256);

    // QKV projections: [16384,1024] x [1024,1024] + bias
    dim3 g1(Hdim / 128, Mtot / 128, 1);
    gemm_kernel<false, true><<<g1, blk>>>(x, Wq, bq, q, Mtot, Hdim, Hdim, 0, 0, 0, 1.0f);
    gemm_kernel<false, true><<<g1, blk>>>(x, Wk, bk, k, Mtot, Hdim, Hdim, 0, 0, 0, 1.0f);
    gemm_kernel<false, true><<<g1, blk>>>(x, Wv, bv, v, Mtot, Hdim, Hdim, 0, 0, 0, 1.0f);

    // energy = Q @ K^T / sqrt(H), per batch
    dim3 g2(Sdim / 128, Sdim / 128, Bdim);
    gemm_kernel<true, false><<<g2, blk>>>(q, k, nullptr, e, Sdim, Sdim, Hdim,
                                          (long long)Sdim * Hdim,
                                          (long long)Sdim * Hdim,
                                          (long long)Sdim * Sdim, 1.0f / 32.0f);

    // softmax over last dim
    softmax_kernel<<<Mtot, 256>>>(e);

    // out = attn @ V, per batch
    dim3 g3(Hdim / 128, Sdim / 128, Bdim);
    gemm_kernel<false, false><<<g3, blk>>>(e, v, nullptr, out, Sdim, Hdim, Sdim,
                                           (long long)Sdim * Sdim,
                                           (long long)Sdim * Hdim,
                                           (long long)Sdim * Hdim, 1.0f);
}

// round 4
// speedup vs baseline: 2.3884x; 2.3884x over previous
#include <cuda_runtime.h>
#include <cuda_fp16.h>
#include <cstdint>

typedef unsigned int u32;
typedef long long ll;

#define Ss 4096
#define Hh 1024
#define MT (4 * Ss)

// ---------------- scratch (device globals; 16B-aligned for cp.async) ----------------
__device__ __align__(256) __half g_xhi[(size_t)MT * Hh];
__device__ __align__(256) __half g_xlo[(size_t)MT * Hh];
__device__ __align__(256) __half g_w[6][(size_t)Hh * Hh]; // Wq hi,lo, Wk hi,lo, Wv hi,lo (row-major)
__device__ __align__(256) __half g_qhi[(size_t)MT * Hh];
__device__ __align__(256) __half g_qlo[(size_t)MT * Hh];
__device__ __align__(256) __half g_khi[(size_t)MT * Hh];
__device__ __align__(256) __half g_klo[(size_t)MT * Hh];
__device__ __align__(256) __half g_vhi[(size_t)MT * Hh];
__device__ __align__(256) __half g_vlo[(size_t)MT * Hh];
__device__ __align__(256) float  g_e[(size_t)4 * Ss * Ss];
__device__ __align__(256) __half g_phi[(size_t)4 * Ss * Ss];
__device__ __align__(256) __half g_plo[(size_t)4 * Ss * Ss];

// ---------------- helpers ----------------
__device__ __forceinline__ u32 s2u(const void* p) {
    u32 a;
    asm("{ .reg .u64 t; cvta.to.shared.u64 t, %1; cvt.u32.u64 %0, t; }" : "=r"(a) : "l"(p));
    return a;
}
__device__ __forceinline__ void cp16(u32 dst, const void* src) {
    asm volatile("cp.async.cg.shared.global [%0], [%1], 16;" :: "r"(dst), "l"(src) : "memory");
}
#define CP_COMMIT() asm volatile("cp.async.commit_group;" ::: "memory")
#define CP_WAIT1()  asm volatile("cp.async.wait_group 1;" ::: "memory")
#define CP_WAIT0()  asm volatile("cp.async.wait_group 0;" ::: "memory")

#define LDSM4(R, addr) \
    asm volatile("ldmatrix.sync.aligned.m8n8.x4.shared.b16 {%0,%1,%2,%3}, [%4];" \
        : "=r"((R)[0]), "=r"((R)[1]), "=r"((R)[2]), "=r"((R)[3]) : "r"(addr))
#define LDSM4T(R, addr) \
    asm volatile("ldmatrix.sync.aligned.m8n8.x4.trans.shared.b16 {%0,%1,%2,%3}, [%4];" \
        : "=r"((R)[0]), "=r"((R)[1]), "=r"((R)[2]), "=r"((R)[3]) : "r"(addr))

#define MMA(d, a, b) \
    asm volatile("mma.sync.aligned.m16n8k16.row.col.f32.f16.f16.f32 " \
        "{%0,%1,%2,%3},{%4,%5,%6,%7},{%8,%9},{%0,%1,%2,%3};" \
        : "+f"((d)[0]), "+f"((d)[1]), "+f"((d)[2]), "+f"((d)[3]) \
        : "r"((a)[0]), "r"((a)[1]), "r"((a)[2]), "r"((a)[3]), "r"((b)[0]), "r"((b)[1]))

__device__ __forceinline__ void split1(float v, __half& h, __half& l) {
    h = __float2half_rn(v);
    l = __float2half_rn(v - __half2float(h));
}

// ---------------- SMEM layout ----------------
// Stage: Ah[128][40] | Al[128][40] | Bh | Bl  (NT pitch 40 halves; NN uses [32][136] in same slot)
#define OPB  10240
#define STGB 40960
#define SMEMB (3 * STGB)

__device__ __forceinline__ void ld_nt(u32 dst, const __half* g, int ld, int r0, int k0, int tid) {
#pragma unroll
    for (int i = 0; i < 2; i++) {
        int e = tid + (i << 8);
        int r = e >> 2, c = e & 3;
        cp16(dst + (u32)((r * 40 + c * 8) * 2), g + (size_t)(r0 + r) * ld + k0 + c * 8);
    }
}
__device__ __forceinline__ void ld_nn(u32 dst, const __half* g, int ld, int n0, int k0, int tid) {
#pragma unroll
    for (int i = 0; i < 2; i++) {
        int e = tid + (i << 8);
        int r = e >> 4, c = e & 15;
        cp16(dst + (u32)((r * 136 + c * 8) * 2), g + (size_t)(k0 + r) * ld + n0 + c * 8);
    }
}

// -------- HMMA GEMM: C = scale*(A @ op(B)) [+ bias], fp16x3 fp32 emulation --------
// A: [M,K] hi/lo row-major. BNN=0: B [N,K] (uses B^T). BNN=1: B [K,N].
// OUTM=0: fp32*scale. OUTM=1: fp16 hi/lo + bias.
template <int BNN, int OUTM>
__global__ __launch_bounds__(256, 1)
void gemm_mma(const __half* __restrict__ Ah, const __half* __restrict__ Al, int lda, ll sA,
              const __half* __restrict__ Bh, const __half* __restrict__ Bl, int ldb, ll sB,
              const float* __restrict__ bias, float scale,
              float* __restrict__ Cf, __half* __restrict__ Chi, __half* __restrict__ Clo,
              int ldc, ll sC, int K)
{
    extern __shared__ char smc[];
    const u32 sb = s2u(smc);
    const int tid = threadIdx.x, wid = tid >> 5, lid = tid & 31;
    const int wm = wid >> 1, wn = wid & 1;
    const int m0 = blockIdx.y * 128, n0 = blockIdx.x * 128, z = blockIdx.z;

    const __half* pAh = Ah + (ll)z * sA;
    const __half* pAl = Al + (ll)z * sA;
    const __half* pBh = Bh + (ll)z * sB;
    const __half* pBl = Bl + (ll)z * sB;

    float acc[64];
#pragma unroll
    for (int i = 0; i < 64; i++) acc[i] = 0.0f;

    const int nc = K >> 5;

    // ldmatrix lane address components (element offsets, constant per thread)
    const int aRow = wm * 32 + (lid & 15);
    const int aColS = (lid >> 4) << 3;
    int bRow, bColS;
    if (BNN) { bRow = (lid & 7) + (((lid >> 3) & 1) << 3); bColS = wn * 64 + ((lid >> 4) << 3); }
    else     { bRow = wn * 64 + (lid & 7) + ((lid >> 4) << 3); bColS = ((lid >> 3) & 1) << 3; }

    // prologue
    {
        u32 b0 = sb;
        ld_nt(b0, pAh, lda, m0, 0, tid);
        ld_nt(b0 + OPB, pAl, lda, m0, 0, tid);
        if (BNN) { ld_nn(b0 + 2 * OPB, pBh, ldb, n0, 0, tid); ld_nn(b0 + 3 * OPB, pBl, ldb, n0, 0, tid); }
        else     { ld_nt(b0 + 2 * OPB, pBh, ldb, n0, 0, tid); ld_nt(b0 + 3 * OPB, pBl, ldb, n0, 0, tid); }
        CP_COMMIT();
        u32 b1 = sb + STGB;
        ld_nt(b1, pAh, lda, m0, 32, tid);
        ld_nt(b1 + OPB, pAl, lda, m0, 32, tid);
        if (BNN) { ld_nn(b1 + 2 * OPB, pBh, ldb, n0, 32, tid); ld_nn(b1 + 3 * OPB, pBl, ldb, n0, 32, tid); }
        else     { ld_nt(b1 + 2 * OPB, pBh, ldb, n0, 32, tid); ld_nt(b1 + 3 * OPB, pBl, ldb, n0, 32, tid); }
        CP_COMMIT();
    }

    int stg = 0;
    for (int j = 0; j < nc; j++) {
        if (j + 2 < nc) CP_WAIT1(); else CP_WAIT0();
        __syncthreads();
        if (j + 2 < nc) {
            int s2 = (j + 2) % 3;
            u32 bs = sb + (u32)s2 * STGB;
            int k0 = (j + 2) << 5;
            ld_nt(bs, pAh, lda, m0, k0, tid);
            ld_nt(bs + OPB, pAl, lda, m0, k0, tid);
            if (BNN) { ld_nn(bs + 2 * OPB, pBh, ldb, n0, k0, tid); ld_nn(bs + 3 * OPB, pBl, ldb, n0, k0, tid); }
            else     { ld_nt(bs + 2 * OPB, pBh, ldb, n0, k0, tid); ld_nt(bs + 3 * OPB, pBl, ldb, n0, k0, tid); }
            CP_COMMIT();
        }
        const u32 sA_ = sb + (u32)stg * STGB;
        const u32 sAh = sA_, sAl = sA_ + OPB, sBh = sA_ + 2 * OPB, sBl = sA_ + 3 * OPB;
#pragma unroll
        for (int kk = 0; kk < 2; kk++) {
            const int kb = kk << 4;
            u32 ah_[8], al_[8], bh_[16], bl_[16];
#pragma unroll
            for (int mi = 0; mi < 2; mi++) {
                u32 off = (u32)(((aRow + mi * 16) * 40 + kb + aColS) * 2);
                LDSM4(ah_ + mi * 4, sAh + off);
                LDSM4(al_ + mi * 4, sAl + off);
            }
#pragma unroll
            for (int p4 = 0; p4 < 4; p4++) {
                if (BNN) {
                    u32 off = (u32)(((kb + bRow) * 136 + bColS + p4 * 16) * 2);
                    LDSM4T(bh_ + p4 * 4, sBh + off);
                    LDSM4T(bl_ + p4 * 4, sBl + off);
                } else {
                    u32 off = (u32)(((bRow + p4 * 16) * 40 + kb + bColS) * 2);
                    LDSM4(bh_ + p4 * 4, sBh + off);
                    LDSM4(bl_ + p4 * 4, sBl + off);
                }
            }
#pragma unroll
            for (int mi = 0; mi < 2; mi++)
#pragma unroll
                for (int nj = 0; nj < 8; nj++) MMA(acc + (mi * 8 + nj) * 4, ah_ + mi * 4, bh_ + nj * 2);
#pragma unroll
            for (int mi = 0; mi < 2; mi++)
#pragma unroll
                for (int nj = 0; nj < 8; nj++) MMA(acc + (mi * 8 + nj) * 4, ah_ + mi * 4, bl_ + nj * 2);
#pragma unroll
            for (int mi = 0; mi < 2; mi++)
#pragma unroll
                for (int nj = 0; nj < 8; nj++) MMA(acc + (mi * 8 + nj) * 4, al_ + mi * 4, bh_ + nj * 2);
        }
        stg = (stg + 1) % 3;
    }

    // -------- epilogue (direct from fragments) --------
    const int g = lid >> 2, t4 = lid & 3;
#pragma unroll
    for (int mi = 0; mi < 2; mi++) {
#pragma unroll
        for (int nj = 0; nj < 8; nj++) {
            const float* c = acc + (mi * 8 + nj) * 4;
            int row = m0 + wm * 32 + mi * 16 + g;
            int col = n0 + wn * 64 + nj * 8 + t4 * 2;
            if (OUTM == 0) {
                size_t base = (size_t)((ll)z * sC) + (size_t)row * ldc + col;
                *(float2*)&Cf[base] = make_float2(c[0] * scale, c[1] * scale);
                *(float2*)&Cf[base + 8 * (size_t)ldc] = make_float2(c[2] * scale, c[3] * scale);
            } else {
                float b0 = bias[col], b1 = bias[col + 1];
                __half h0, h1, l0, l1;
                split1(c[0] + b0, h0, l0); split1(c[1] + b1, h1, l1);
                size_t o = (size_t)row * ldc + col;
                *(__half2*)&Chi[o] = __halves2half2(h0, h1);
                *(__half2*)&Clo[o] = __halves2half2(l0, l1);
                split1(c[2] + b0, h0, l0); split1(c[3] + b1, h1, l1);
                o += 8 * (size_t)ldc;
                *(__half2*)&Chi[o] = __halves2half2(h0, h1);
                *(__half2*)&Clo[o] = __halves2half2(l0, l1);
            }
        }
    }
}

// ---------------- elementwise ----------------
__global__ void split_f(const float* __restrict__ in, __half* __restrict__ hi, __half* __restrict__ lo) {
    size_t i = (size_t)blockIdx.x * blockDim.x + threadIdx.x; // one float4
    float4 v = ((const float4*)in)[i];
    __half h0, h1, h2, h3, l0, l1, l2, l3;
    split1(v.x, h0, l0); split1(v.y, h1, l1); split1(v.z, h2, l2); split1(v.w, h3, l3);
    ((__half2*)hi)[2 * i]     = __halves2half2(h0, h1);
    ((__half2*)hi)[2 * i + 1] = __halves2half2(h2, h3);
    ((__half2*)lo)[2 * i]     = __halves2half2(l0, l1);
    ((__half2*)lo)[2 * i + 1] = __halves2half2(l2, l3);
}

__global__ void softmax_split(const float* __restrict__ e, __half* __restrict__ phi, __half* __restrict__ plo) {
    const size_t row = blockIdx.x;
    const float4* p = (const float4*)(e + row * Ss);
    const int t = threadIdx.x;
    float4 v[4];
    float mx = -1e30f;
#pragma unroll
    for (int c = 0; c < 4; c++) {
        v[c] = p[t + c * 256];
        mx = fmaxf(mx, fmaxf(fmaxf(v[c].x, v[c].y), fmaxf(v[c].z, v[c].w)));
    }
    __shared__ float red[256];
    red[t] = mx; __syncthreads();
    for (int s = 128; s > 0; s >>= 1) { if (t < s) red[t] = fmaxf(red[t], red[t + s]); __syncthreads(); }
    mx = red[0]; __syncthreads();
    float sum = 0.0f;
#pragma unroll
    for (int c = 0; c < 4; c++) {
        v[c].x = __expf(v[c].x - mx); v[c].y = __expf(v[c].y - mx);
        v[c].z = __expf(v[c].z - mx); v[c].w = __expf(v[c].w - mx);
        sum += v[c].x + v[c].y + v[c].z + v[c].w;
    }
    red[t] = sum; __syncthreads();
    for (int s = 128; s > 0; s >>= 1) { if (t < s) red[t] += red[t + s]; __syncthreads(); }
    const float inv = 1.0f / red[0];
    __half2* ph = (__half2*)(phi + row * Ss);
    __half2* pl = (__half2*)(plo + row * Ss);
#pragma unroll
    for (int c = 0; c < 4; c++) {
        __half h0, h1, h2, h3, l0, l1, l2, l3;
        split1(v[c].x * inv, h0, l0); split1(v[c].y * inv, h1, l1);
        split1(v[c].z * inv, h2, l2); split1(v[c].w * inv, h3, l3);
        int idx = t + c * 256;
        ph[2 * idx] = __halves2half2(h0, h1); ph[2 * idx + 1] = __halves2half2(h2, h3);
        pl[2 * idx] = __halves2half2(l0, l1); pl[2 * idx + 1] = __halves2half2(l2, l3);
    }
}

// ---------------- host ----------------
extern "C" void kernel_launch(void* const* d_in, const int* in_sizes, int n_in,
                              void* d_out, int out_size)
{
    const float* x  = (const float*)d_in[0];
    const float* Wq = (const float*)d_in[1];
    const float* bq = (const float*)d_in[2];
    const float* Wk = (const float*)d_in[3];
    const float* bk = (const float*)d_in[4];
    const float* Wv = (const float*)d_in[5];
    const float* bv = (const float*)d_in[6];
    float* out = (float*)d_out;

    __half *xhi, *xlo, *w, *qhi, *qlo, *khi, *klo, *vhi, *vlo, *phi, *plo;
    float* e;
    cudaGetSymbolAddress((void**)&xhi, g_xhi);
    cudaGetSymbolAddress((void**)&xlo, g_xlo);
    cudaGetSymbolAddress((void**)&w,   g_w);
    cudaGetSymbolAddress((void**)&qhi, g_qhi);
    cudaGetSymbolAddress((void**)&qlo, g_qlo);
    cudaGetSymbolAddress((void**)&khi, g_khi);
    cudaGetSymbolAddress((void**)&klo, g_klo);
    cudaGetSymbolAddress((void**)&vhi, g_vhi);
    cudaGetSymbolAddress((void**)&vlo, g_vlo);
    cudaGetSymbolAddress((void**)&e,   g_e);
    cudaGetSymbolAddress((void**)&phi, g_phi);
    cudaGetSymbolAddress((void**)&plo, g_plo);

    cudaFuncSetAttribute(gemm_mma<1, 1>, cudaFuncAttributeMaxDynamicSharedMemorySize, SMEMB);
    cudaFuncSetAttribute(gemm_mma<0, 0>, cudaFuncAttributeMaxDynamicSharedMemorySize, SMEMB);
    cudaFuncSetAttribute(gemm_mma<1, 0>, cudaFuncAttributeMaxDynamicSharedMemorySize, SMEMB);

    const size_t HH = (size_t)Hh * Hh;

    split_f<<<(size_t)MT * Hh / 1024, 256>>>(x, xhi, xlo);
    split_f<<<HH / 1024, 256>>>(Wq, w + 0 * HH, w + 1 * HH);
    split_f<<<HH / 1024, 256>>>(Wk, w + 2 * HH, w + 3 * HH);
    split_f<<<HH / 1024, 256>>>(Wv, w + 4 * HH, w + 5 * HH);

    // projections: C = x @ W + b  (B NN), fp16 hi/lo out
    dim3 gp(8, 128, 1);
    gemm_mma<1, 1><<<gp, 256, SMEMB>>>(xhi, xlo, Hh, 0, w + 0 * HH, w + 1 * HH, Hh, 0,
                                       bq, 1.0f, nullptr, qhi, qlo, Hh, 0, Hh);
    gemm_mma<1, 1><<<gp, 256, SMEMB>>>(xhi, xlo, Hh, 0, w + 2 * HH, w + 3 * HH, Hh, 0,
                                       bk, 1.0f, nullptr, khi, klo, Hh, 0, Hh);
    gemm_mma<1, 1><<<gp, 256, SMEMB>>>(xhi, xlo, Hh, 0, w + 4 * HH, w + 5 * HH, Hh, 0,
                                       bv, 1.0f, nullptr, vhi, vlo, Hh, 0, Hh);

    // energy = Q @ K^T / 32 (B NT), fp32 out, per-batch
    gemm_mma<0, 0><<<dim3(32, 32, 4), 256, SMEMB>>>(qhi, qlo, Hh, (ll)Ss * Hh,
                                                    khi, klo, Hh, (ll)Ss * Hh,
                                                    nullptr, 1.0f / 32.0f, e, nullptr, nullptr,
                                                    Ss, (ll)Ss * Ss, Hh);
    softmax_split<<<MT, 256>>>(e, phi, plo);

    // out = P @ V (B NN), fp32 out, per-batch
    gemm_mma<1, 0><<<dim3(8, 32, 4), 256, SMEMB>>>(phi, plo, Ss, (ll)Ss * Ss,
                                                   vhi, vlo, Hh, (ll)Ss * Hh,
                                                   nullptr, 1.0f, out, nullptr, nullptr,
                                                   Hh, (ll)Ss * Hh, Ss);
}

// round 5
// speedup vs baseline: 2.6587x; 1.1131x over previous
#include <cuda_runtime.h>
#include <cuda_fp16.h>
#include <cstdint>

typedef unsigned int u32;
typedef long long ll;

#define Ss 4096
#define Hh 1024
#define MT (4 * Ss)

// ---------------- scratch ----------------
__device__ __align__(256) __half g_xhi[(size_t)MT * Hh];
__device__ __align__(256) __half g_xlo[(size_t)MT * Hh];
__device__ __align__(256) __half g_w[6][(size_t)Hh * Hh];      // (Wq,Wk,Wv) x (hi,lo)
__device__ __align__(256) __half g_qkvhi[3][(size_t)MT * Hh];  // q,k,v hi
__device__ __align__(256) __half g_qkvlo[3][(size_t)MT * Hh];  // q,k,v lo
__device__ __align__(256) float  g_e[(size_t)4 * Ss * Ss];
__device__ __align__(256) __half g_phi[(size_t)4 * Ss * Ss];
__device__ __align__(256) __half g_plo[(size_t)4 * Ss * Ss];

// ---------------- helpers ----------------
__device__ __forceinline__ u32 s2u(const void* p) {
    u32 a;
    asm("{ .reg .u64 t; cvta.to.shared.u64 t, %1; cvt.u32.u64 %0, t; }" : "=r"(a) : "l"(p));
    return a;
}
__device__ __forceinline__ void cp16(u32 dst, const void* src) {
    asm volatile("cp.async.cg.shared.global [%0], [%1], 16;" :: "r"(dst), "l"(src) : "memory");
}
#define CP_COMMIT() asm volatile("cp.async.commit_group;" ::: "memory")
#define CP_WAIT1()  asm volatile("cp.async.wait_group 1;" ::: "memory")
#define CP_WAIT0()  asm volatile("cp.async.wait_group 0;" ::: "memory")

#define LDSM4(R, addr) \
    asm volatile("ldmatrix.sync.aligned.m8n8.x4.shared.b16 {%0,%1,%2,%3}, [%4];" \
        : "=r"((R)[0]), "=r"((R)[1]), "=r"((R)[2]), "=r"((R)[3]) : "r"(addr))
#define LDSM4T(R, addr) \
    asm volatile("ldmatrix.sync.aligned.m8n8.x4.trans.shared.b16 {%0,%1,%2,%3}, [%4];" \
        : "=r"((R)[0]), "=r"((R)[1]), "=r"((R)[2]), "=r"((R)[3]) : "r"(addr))

#define MMA(d, a, b) \
    asm volatile("mma.sync.aligned.m16n8k16.row.col.f32.f16.f16.f32 " \
        "{%0,%1,%2,%3},{%4,%5,%6,%7},{%8,%9},{%0,%1,%2,%3};" \
        : "+f"((d)[0]), "+f"((d)[1]), "+f"((d)[2]), "+f"((d)[3]) \
        : "r"((a)[0]), "r"((a)[1]), "r"((a)[2]), "r"((a)[3]), "r"((b)[0]), "r"((b)[1]))

__device__ __forceinline__ void split1(float v, __half& h, __half& l) {
    h = __float2half_rn(v);
    l = __float2half_rn(v - __half2float(h));
}

// ---------------- SMEM layout: K-chunk 64, 3 stages ----------------
// NT operand: 128 rows x 64 halves, pitch 72 halves (144B). 18432 B.
// NN operand: 64 rows x 128 halves, pitch 136 halves (272B). 17408 B (fits in 18432 slot).
#define OPB  18432
#define STGB (4 * OPB)
#define SMEMB (3 * STGB)

// NT load: 16KB, 4 cp16/thread; lanes 0-7 fill one 128B row -> conflict-free writes
__device__ __forceinline__ void ld_nt(u32 dst, const __half* g, int ld, int r0, int k0, int tid) {
#pragma unroll
    for (int i = 0; i < 4; i++) {
        int e = tid + (i << 8);
        int r = e >> 3, c = e & 7;
        cp16(dst + (u32)(r * 144 + c * 16), g + (size_t)(r0 + r) * ld + k0 + c * 8);
    }
}
// NN load: 16KB, 4 cp16/thread
__device__ __forceinline__ void ld_nn(u32 dst, const __half* g, int ld, int n0, int k0, int tid) {
#pragma unroll
    for (int i = 0; i < 4; i++) {
        int e = tid + (i << 8);
        int r = e >> 4, c = e & 15;
        cp16(dst + (u32)(r * 272 + c * 16), g + (size_t)(k0 + r) * ld + n0 + c * 8);
    }
}

// -------- HMMA GEMM: C = scale*(A @ op(B)) [+ bias], fp16x3 fp32 emulation --------
// BNN=0: B [N,K] (B^T). BNN=1: B [K,N]. OUTM=0: fp32*scale. OUTM=1: fp16 hi/lo + bias.
// blockIdx.z advances A by sA, B by sB, C by sC, and selects bias b0/b1/b2.
template <int BNN, int OUTM>
__global__ __launch_bounds__(256, 1)
void gemm_mma(const __half* __restrict__ Ah, const __half* __restrict__ Al, int lda, ll sA,
              const __half* __restrict__ Bh, const __half* __restrict__ Bl, int ldb, ll sB,
              const float* __restrict__ b0, const float* __restrict__ b1,
              const float* __restrict__ b2, float scale,
              float* __restrict__ Cf, __half* __restrict__ Chi, __half* __restrict__ Clo,
              int ldc, ll sC, int K)
{
    extern __shared__ __align__(16) char smc[];
    const u32 sb = s2u(smc);
    const int tid = threadIdx.x, wid = tid >> 5, lid = tid & 31;
    const int wm = wid >> 1, wn = wid & 1;
    const int m0 = blockIdx.y * 128, n0 = blockIdx.x * 128, z = blockIdx.z;

    const __half* pAh = Ah + (ll)z * sA;
    const __half* pAl = Al + (ll)z * sA;
    const __half* pBh = Bh + (ll)z * sB;
    const __half* pBl = Bl + (ll)z * sB;
    const float* bias = (z == 0) ? b0 : ((z == 1) ? b1 : b2);

    float acc[64];
#pragma unroll
    for (int i = 0; i < 64; i++) acc[i] = 0.0f;

    const int nc = K >> 6;

    const int aRow = wm * 32 + (lid & 15);
    const int aColS = (lid >> 4) << 3;
    int bRow, bColS;
    if (BNN) { bRow = (lid & 7) + (((lid >> 3) & 1) << 3); bColS = wn * 64 + ((lid >> 4) << 3); }
    else     { bRow = wn * 64 + (lid & 7) + ((lid >> 4) << 3); bColS = ((lid >> 3) & 1) << 3; }

    // prologue: stages 0,1 <- chunks 0,1
#pragma unroll
    for (int j = 0; j < 2; j++) {
        u32 bs = sb + (u32)j * STGB;
        int k0 = j << 6;
        ld_nt(bs, pAh, lda, m0, k0, tid);
        ld_nt(bs + OPB, pAl, lda, m0, k0, tid);
        if (BNN) { ld_nn(bs + 2 * OPB, pBh, ldb, n0, k0, tid); ld_nn(bs + 3 * OPB, pBl, ldb, n0, k0, tid); }
        else     { ld_nt(bs + 2 * OPB, pBh, ldb, n0, k0, tid); ld_nt(bs + 3 * OPB, pBl, ldb, n0, k0, tid); }
        CP_COMMIT();
    }

    int stg = 0;
    for (int j = 0; j < nc; j++) {
        if (j + 2 < nc) CP_WAIT1(); else CP_WAIT0();
        __syncthreads();
        if (j + 2 < nc) {
            int s2 = (j + 2) % 3;
            u32 bs = sb + (u32)s2 * STGB;
            int k0 = (j + 2) << 6;
            ld_nt(bs, pAh, lda, m0, k0, tid);
            ld_nt(bs + OPB, pAl, lda, m0, k0, tid);
            if (BNN) { ld_nn(bs + 2 * OPB, pBh, ldb, n0, k0, tid); ld_nn(bs + 3 * OPB, pBl, ldb, n0, k0, tid); }
            else     { ld_nt(bs + 2 * OPB, pBh, ldb, n0, k0, tid); ld_nt(bs + 3 * OPB, pBl, ldb, n0, k0, tid); }
            CP_COMMIT();
        }
        const u32 sS = sb + (u32)stg * STGB;
        const u32 sAh = sS, sAl = sS + OPB, sBh = sS + 2 * OPB, sBl = sS + 3 * OPB;
#pragma unroll
        for (int kk = 0; kk < 4; kk++) {
            const int kb = kk << 4;
            u32 ah_[8], al_[8], bh_[16], bl_[16];
#pragma unroll
            for (int mi = 0; mi < 2; mi++) {
                u32 off = (u32)(((aRow + mi * 16) * 72 + kb + aColS) * 2);
                LDSM4(ah_ + mi * 4, sAh + off);
                LDSM4(al_ + mi * 4, sAl + off);
            }
#pragma unroll
            for (int p4 = 0; p4 < 4; p4++) {
                if (BNN) {
                    u32 off = (u32)(((kb + bRow) * 136 + bColS + p4 * 16) * 2);
                    LDSM4T(bh_ + p4 * 4, sBh + off);
                    LDSM4T(bl_ + p4 * 4, sBl + off);
                } else {
                    u32 off = (u32)(((bRow + p4 * 16) * 72 + kb + bColS) * 2);
                    LDSM4(bh_ + p4 * 4, sBh + off);
                    LDSM4(bl_ + p4 * 4, sBl + off);
                }
            }
#pragma unroll
            for (int mi = 0; mi < 2; mi++)
#pragma unroll
                for (int nj = 0; nj < 8; nj++) MMA(acc + (mi * 8 + nj) * 4, ah_ + mi * 4, bh_ + nj * 2);
#pragma unroll
            for (int mi = 0; mi < 2; mi++)
#pragma unroll
                for (int nj = 0; nj < 8; nj++) MMA(acc + (mi * 8 + nj) * 4, ah_ + mi * 4, bl_ + nj * 2);
#pragma unroll
            for (int mi = 0; mi < 2; mi++)
#pragma unroll
                for (int nj = 0; nj < 8; nj++) MMA(acc + (mi * 8 + nj) * 4, al_ + mi * 4, bh_ + nj * 2);
        }
        stg = (stg + 1) % 3;
    }

    // -------- epilogue --------
    const int g = lid >> 2, t4 = lid & 3;
#pragma unroll
    for (int mi = 0; mi < 2; mi++) {
#pragma unroll
        for (int nj = 0; nj < 8; nj++) {
            const float* c = acc + (mi * 8 + nj) * 4;
            int row = m0 + wm * 32 + mi * 16 + g;
            int col = n0 + wn * 64 + nj * 8 + t4 * 2;
            if (OUTM == 0) {
                size_t base = (size_t)((ll)z * sC) + (size_t)row * ldc + col;
                *(float2*)&Cf[base] = make_float2(c[0] * scale, c[1] * scale);
                *(float2*)&Cf[base + 8 * (size_t)ldc] = make_float2(c[2] * scale, c[3] * scale);
            } else {
                float bb0 = bias[col], bb1 = bias[col + 1];
                __half h0, h1, l0, l1;
                size_t o = (size_t)((ll)z * sC) + (size_t)row * ldc + col;
                split1(c[0] + bb0, h0, l0); split1(c[1] + bb1, h1, l1);
                *(__half2*)&Chi[o] = __halves2half2(h0, h1);
                *(__half2*)&Clo[o] = __halves2half2(l0, l1);
                split1(c[2] + bb0, h0, l0); split1(c[3] + bb1, h1, l1);
                o += 8 * (size_t)ldc;
                *(__half2*)&Chi[o] = __halves2half2(h0, h1);
                *(__half2*)&Clo[o] = __halves2half2(l0, l1);
            }
        }
    }
}

// ---------------- elementwise ----------------
__global__ void split_f(const float* __restrict__ in, __half* __restrict__ hi, __half* __restrict__ lo) {
    size_t i = (size_t)blockIdx.x * blockDim.x + threadIdx.x;
    float4 v = ((const float4*)in)[i];
    __half h0, h1, h2, h3, l0, l1, l2, l3;
    split1(v.x, h0, l0); split1(v.y, h1, l1); split1(v.z, h2, l2); split1(v.w, h3, l3);
    ((__half2*)hi)[2 * i]     = __halves2half2(h0, h1);
    ((__half2*)hi)[2 * i + 1] = __halves2half2(h2, h3);
    ((__half2*)lo)[2 * i]     = __halves2half2(l0, l1);
    ((__half2*)lo)[2 * i + 1] = __halves2half2(l2, l3);
}

__global__ void softmax_split(const float* __restrict__ e, __half* __restrict__ phi, __half* __restrict__ plo) {
    const size_t row = blockIdx.x;
    const float4* p = (const float4*)(e + row * Ss);
    const int t = threadIdx.x;
    float4 v[4];
    float mx = -1e30f;
#pragma unroll
    for (int c = 0; c < 4; c++) {
        v[c] = p[t + c * 256];
        mx = fmaxf(mx, fmaxf(fmaxf(v[c].x, v[c].y), fmaxf(v[c].z, v[c].w)));
    }
    __shared__ float red[256];
    red[t] = mx; __syncthreads();
    for (int s = 128; s > 0; s >>= 1) { if (t < s) red[t] = fmaxf(red[t], red[t + s]); __syncthreads(); }
    mx = red[0]; __syncthreads();
    float sum = 0.0f;
#pragma unroll
    for (int c = 0; c < 4; c++) {
        v[c].x = __expf(v[c].x - mx); v[c].y = __expf(v[c].y - mx);
        v[c].z = __expf(v[c].z - mx); v[c].w = __expf(v[c].w - mx);
        sum += v[c].x + v[c].y + v[c].z + v[c].w;
    }
    red[t] = sum; __syncthreads();
    for (int s = 128; s > 0; s >>= 1) { if (t < s) red[t] += red[t + s]; __syncthreads(); }
    const float inv = 1.0f / red[0];
    __half2* ph = (__half2*)(phi + row * Ss);
    __half2* pl = (__half2*)(plo + row * Ss);
#pragma unroll
    for (int c = 0; c < 4; c++) {
        __half h0, h1, h2, h3, l0, l1, l2, l3;
        split1(v[c].x * inv, h0, l0); split1(v[c].y * inv, h1, l1);
        split1(v[c].z * inv, h2, l2); split1(v[c].w * inv, h3, l3);
        int idx = t + c * 256;
        ph[2 * idx] = __halves2half2(h0, h1); ph[2 * idx + 1] = __halves2half2(h2, h3);
        pl[2 * idx] = __halves2half2(l0, l1); pl[2 * idx + 1] = __halves2half2(l2, l3);
    }
}

// ---------------- host ----------------
extern "C" void kernel_launch(void* const* d_in, const int* in_sizes, int n_in,
                              void* d_out, int out_size)
{
    const float* x  = (const float*)d_in[0];
    const float* Wq = (const float*)d_in[1];
    const float* bq = (const float*)d_in[2];
    const float* Wk = (const float*)d_in[3];
    const float* bk = (const float*)d_in[4];
    const float* Wv = (const float*)d_in[5];
    const float* bv = (const float*)d_in[6];
    float* out = (float*)d_out;

    __half *xhi, *xlo, *w, *qkvhi, *qkvlo, *phi, *plo;
    float* e;
    cudaGetSymbolAddress((void**)&xhi, g_xhi);
    cudaGetSymbolAddress((void**)&xlo, g_xlo);
    cudaGetSymbolAddress((void**)&w,   g_w);
    cudaGetSymbolAddress((void**)&qkvhi, g_qkvhi);
    cudaGetSymbolAddress((void**)&qkvlo, g_qkvlo);
    cudaGetSymbolAddress((void**)&e,   g_e);
    cudaGetSymbolAddress((void**)&phi, g_phi);
    cudaGetSymbolAddress((void**)&plo, g_plo);

    cudaFuncSetAttribute(gemm_mma<1, 1>, cudaFuncAttributeMaxDynamicSharedMemorySize, SMEMB);
    cudaFuncSetAttribute(gemm_mma<0, 0>, cudaFuncAttributeMaxDynamicSharedMemorySize, SMEMB);
    cudaFuncSetAttribute(gemm_mma<1, 0>, cudaFuncAttributeMaxDynamicSharedMemorySize, SMEMB);

    const size_t HH = (size_t)Hh * Hh;
    const size_t QKV = (size_t)MT * Hh;

    split_f<<<(size_t)MT * Hh / 1024, 256>>>(x, xhi, xlo);
    split_f<<<HH / 1024, 256>>>(Wq, w + 0 * HH, w + 1 * HH);
    split_f<<<HH / 1024, 256>>>(Wk, w + 2 * HH, w + 3 * HH);
    split_f<<<HH / 1024, 256>>>(Wv, w + 4 * HH, w + 5 * HH);

    // merged projections: z in {0,1,2} -> q,k,v = x @ W_z + b_z (fp16 hi/lo out)
    gemm_mma<1, 1><<<dim3(8, 128, 3), 256, SMEMB>>>(
        xhi, xlo, Hh, 0,
        w, w + HH, Hh, (ll)(2 * HH),
        bq, bk, bv, 1.0f,
        nullptr, qkvhi, qkvlo, Hh, (ll)QKV, Hh);

    // energy = Q @ K^T / 32 (B NT), fp32 out, per-batch
    gemm_mma<0, 0><<<dim3(32, 32, 4), 256, SMEMB>>>(
        qkvhi, qkvlo, Hh, (ll)Ss * Hh,
        qkvhi + QKV, qkvlo + QKV, Hh, (ll)Ss * Hh,
        nullptr, nullptr, nullptr, 1.0f / 32.0f,
        e, nullptr, nullptr, Ss, (ll)Ss * Ss, Hh);

    softmax_split<<<MT, 256>>>(e, phi, plo);

    // out = P @ V (B NN), fp32 out, per-batch
    gemm_mma<1, 0><<<dim3(8, 32, 4), 256, SMEMB>>>(
        phi, plo, Ss, (ll)Ss * Ss,
        qkvhi + 2 * QKV, qkvlo + 2 * QKV, Hh, (ll)Ss * Hh,
        nullptr, nullptr, nullptr, 1.0f,
        out, nullptr, nullptr, Hh, (ll)Ss * Hh, Ss);
}

// round 6
// speedup vs baseline: 2.6625x; 1.0014x over previous
#include <cuda_runtime.h>
#include <cuda_fp16.h>
#include <cstdint>

typedef unsigned int u32;
typedef long long ll;

#define Ss 4096
#define Hh 1024
#define MT (4 * Ss)

// ---------------- scratch ----------------
__device__ __align__(256) __half g_xhi[(size_t)MT * Hh];
__device__ __align__(256) __half g_xlo[(size_t)MT * Hh];
__device__ __align__(256) __half g_w[6][(size_t)Hh * Hh];      // (Wq,Wk,Wv) x (hi,lo)
__device__ __align__(256) __half g_qkvhi[3][(size_t)MT * Hh];
__device__ __align__(256) __half g_qkvlo[3][(size_t)MT * Hh];
__device__ __align__(256) float  g_e[(size_t)4 * Ss * Ss];
__device__ __align__(256) __half g_phi[(size_t)4 * Ss * Ss];
__device__ __align__(256) __half g_plo[(size_t)4 * Ss * Ss];

// ---------------- helpers ----------------
__device__ __forceinline__ u32 s2u(const void* p) {
    u32 a;
    asm("{ .reg .u64 t; cvta.to.shared.u64 t, %1; cvt.u32.u64 %0, t; }" : "=r"(a) : "l"(p));
    return a;
}
__device__ __forceinline__ void cp16(u32 dst, const void* src) {
    asm volatile("cp.async.cg.shared.global [%0], [%1], 16;" :: "r"(dst), "l"(src) : "memory");
}
#define CP_COMMIT() asm volatile("cp.async.commit_group;" ::: "memory")
#define CP_WAIT1()  asm volatile("cp.async.wait_group 1;" ::: "memory")
#define CP_WAIT0()  asm volatile("cp.async.wait_group 0;" ::: "memory")

#define LDSM4(R, addr) \
    asm volatile("ldmatrix.sync.aligned.m8n8.x4.shared.b16 {%0,%1,%2,%3}, [%4];" \
        : "=r"((R)[0]), "=r"((R)[1]), "=r"((R)[2]), "=r"((R)[3]) : "r"(addr))
#define LDSM4T(R, addr) \
    asm volatile("ldmatrix.sync.aligned.m8n8.x4.trans.shared.b16 {%0,%1,%2,%3}, [%4];" \
        : "=r"((R)[0]), "=r"((R)[1]), "=r"((R)[2]), "=r"((R)[3]) : "r"(addr))

#define MMA_(d, a, b) \
    asm volatile("mma.sync.aligned.m16n8k16.row.col.f32.f16.f16.f32 " \
        "{%0,%1,%2,%3},{%4,%5,%6,%7},{%8,%9},{%0,%1,%2,%3};" \
        : "+f"((d)[0]), "+f"((d)[1]), "+f"((d)[2]), "+f"((d)[3]) \
        : "r"((a)[0]), "r"((a)[1]), "r"((a)[2]), "r"((a)[3]), "r"((b)[0]), "r"((b)[1]))

__device__ __forceinline__ void split1(float v, __half& h, __half& l) {
    h = __float2half_rn(v);
    l = __float2half_rn(v - __half2float(h));
}

// ---------------- SMEM layout: K-chunk 64, 3 stages ----------------
#define OPB  18432
#define STGB (4 * OPB)
#define SMEMB (3 * STGB)

__device__ __forceinline__ void ld_nt(u32 dst, const __half* g, int ld, int r0, int k0, int tid) {
#pragma unroll
    for (int i = 0; i < 4; i++) {
        int e = tid + (i << 8);
        int r = e >> 3, c = e & 7;
        cp16(dst + (u32)(r * 144 + c * 16), g + (size_t)(r0 + r) * ld + k0 + c * 8);
    }
}
__device__ __forceinline__ void ld_nn(u32 dst, const __half* g, int ld, int n0, int k0, int tid) {
#pragma unroll
    for (int i = 0; i < 4; i++) {
        int e = tid + (i << 8);
        int r = e >> 4, c = e & 15;
        cp16(dst + (u32)(r * 272 + c * 16), g + (size_t)(k0 + r) * ld + n0 + c * 8);
    }
}

// fragment load for one 16-wide K slice (fully inlined; constant indices keep regs)
template <int BNN>
__device__ __forceinline__ void load_frags(u32 sAh, u32 sAl, u32 sBh, u32 sBl, int kb,
                                           int aRow, int aColS, int bRow, int bColS,
                                           u32* ah, u32* al, u32* bh, u32* bl)
{
#pragma unroll
    for (int mi = 0; mi < 2; mi++) {
        u32 off = (u32)(((aRow + mi * 16) * 72 + kb + aColS) * 2);
        LDSM4(ah + mi * 4, sAh + off);
        LDSM4(al + mi * 4, sAl + off);
    }
#pragma unroll
    for (int p4 = 0; p4 < 4; p4++) {
        if (BNN) {
            u32 off = (u32)(((kb + bRow) * 136 + bColS + p4 * 16) * 2);
            LDSM4T(bh + p4 * 4, sBh + off);
            LDSM4T(bl + p4 * 4, sBl + off);
        } else {
            u32 off = (u32)(((bRow + p4 * 16) * 72 + kb + bColS) * 2);
            LDSM4(bh + p4 * 4, sBh + off);
            LDSM4(bl + p4 * 4, sBl + off);
        }
    }
}

__device__ __forceinline__ void mma_all(float* acc, const u32* ah, const u32* al,
                                        const u32* bh, const u32* bl)
{
#pragma unroll
    for (int mi = 0; mi < 2; mi++)
#pragma unroll
        for (int nj = 0; nj < 8; nj++) MMA_(acc + (mi * 8 + nj) * 4, ah + mi * 4, bh + nj * 2);
#pragma unroll
    for (int mi = 0; mi < 2; mi++)
#pragma unroll
        for (int nj = 0; nj < 8; nj++) MMA_(acc + (mi * 8 + nj) * 4, ah + mi * 4, bl + nj * 2);
#pragma unroll
    for (int mi = 0; mi < 2; mi++)
#pragma unroll
        for (int nj = 0; nj < 8; nj++) MMA_(acc + (mi * 8 + nj) * 4, al + mi * 4, bh + nj * 2);
}

// -------- HMMA GEMM: C = scale*(A @ op(B)) [+ bias], fp16x3 fp32 emulation --------
template <int BNN, int OUTM>
__global__ __launch_bounds__(256, 1)
void gemm_mma(const __half* __restrict__ Ah, const __half* __restrict__ Al, int lda, ll sA,
              const __half* __restrict__ Bh, const __half* __restrict__ Bl, int ldb, ll sB,
              const float* __restrict__ b0, const float* __restrict__ b1,
              const float* __restrict__ b2, float scale,
              float* __restrict__ Cf, __half* __restrict__ Chi, __half* __restrict__ Clo,
              int ldc, ll sC, int K)
{
    extern __shared__ __align__(16) char smc[];
    const u32 sb = s2u(smc);
    const int tid = threadIdx.x, wid = tid >> 5, lid = tid & 31;
    const int wm = wid >> 1, wn = wid & 1;
    const int m0 = blockIdx.y * 128, n0 = blockIdx.x * 128, z = blockIdx.z;

    const __half* pAh = Ah + (ll)z * sA;
    const __half* pAl = Al + (ll)z * sA;
    const __half* pBh = Bh + (ll)z * sB;
    const __half* pBl = Bl + (ll)z * sB;
    const float* bias = (z == 0) ? b0 : ((z == 1) ? b1 : b2);

    float acc[64];
#pragma unroll
    for (int i = 0; i < 64; i++) acc[i] = 0.0f;

    const int nc = K >> 6;

    const int aRow = wm * 32 + (lid & 15);
    const int aColS = (lid >> 4) << 3;
    int bRow, bColS;
    if (BNN) { bRow = (lid & 7) + (((lid >> 3) & 1) << 3); bColS = wn * 64 + ((lid >> 4) << 3); }
    else     { bRow = wn * 64 + (lid & 7) + ((lid >> 4) << 3); bColS = ((lid >> 3) & 1) << 3; }

    // prologue: stages 0,1 <- chunks 0,1
#pragma unroll
    for (int j = 0; j < 2; j++) {
        u32 bs = sb + (u32)j * STGB;
        int k0 = j << 6;
        ld_nt(bs, pAh, lda, m0, k0, tid);
        ld_nt(bs + OPB, pAl, lda, m0, k0, tid);
        if (BNN) { ld_nn(bs + 2 * OPB, pBh, ldb, n0, k0, tid); ld_nn(bs + 3 * OPB, pBl, ldb, n0, k0, tid); }
        else     { ld_nt(bs + 2 * OPB, pBh, ldb, n0, k0, tid); ld_nt(bs + 3 * OPB, pBl, ldb, n0, k0, tid); }
        CP_COMMIT();
    }

    u32 fah[2][8], fal[2][8], fbh[2][16], fbl[2][16];

    int stg = 0;
    for (int j = 0; j < nc; j++) {
        if (j + 2 < nc) CP_WAIT1(); else CP_WAIT0();
        __syncthreads();
        if (j + 2 < nc) {
            int s2 = (j + 2) % 3;
            u32 bs = sb + (u32)s2 * STGB;
            int k0 = (j + 2) << 6;
            ld_nt(bs, pAh, lda, m0, k0, tid);
            ld_nt(bs + OPB, pAl, lda, m0, k0, tid);
            if (BNN) { ld_nn(bs + 2 * OPB, pBh, ldb, n0, k0, tid); ld_nn(bs + 3 * OPB, pBl, ldb, n0, k0, tid); }
            else     { ld_nt(bs + 2 * OPB, pBh, ldb, n0, k0, tid); ld_nt(bs + 3 * OPB, pBl, ldb, n0, k0, tid); }
            CP_COMMIT();
        }
        const u32 sS = sb + (u32)stg * STGB;
        const u32 sAh = sS, sAl = sS + OPB, sBh = sS + 2 * OPB, sBl = sS + 3 * OPB;

        // software-pipelined fragments: load kk+1 while MMAs of kk run
        load_frags<BNN>(sAh, sAl, sBh, sBl, 0, aRow, aColS, bRow, bColS,
                        fah[0], fal[0], fbh[0], fbl[0]);
#pragma unroll
        for (int kk = 0; kk < 4; kk++) {
            const int cur = kk & 1, nxt = cur ^ 1;
            if (kk < 3)
                load_frags<BNN>(sAh, sAl, sBh, sBl, (kk + 1) << 4, aRow, aColS, bRow, bColS,
                                fah[nxt], fal[nxt], fbh[nxt], fbl[nxt]);
            mma_all(acc, fah[cur], fal[cur], fbh[cur], fbl[cur]);
        }
        stg = (stg + 1) % 3;
    }

    // -------- epilogue --------
    const int g = lid >> 2, t4 = lid & 3;
#pragma unroll
    for (int mi = 0; mi < 2; mi++) {
#pragma unroll
        for (int nj = 0; nj < 8; nj++) {
            const float* c = acc + (mi * 8 + nj) * 4;
            int row = m0 + wm * 32 + mi * 16 + g;
            int col = n0 + wn * 64 + nj * 8 + t4 * 2;
            if (OUTM == 0) {
                size_t base = (size_t)((ll)z * sC) + (size_t)row * ldc + col;
                *(float2*)&Cf[base] = make_float2(c[0] * scale, c[1] * scale);
                *(float2*)&Cf[base + 8 * (size_t)ldc] = make_float2(c[2] * scale, c[3] * scale);
            } else {
                float bb0 = bias[col], bb1 = bias[col + 1];
                __half h0, h1, l0, l1;
                size_t o = (size_t)((ll)z * sC) + (size_t)row * ldc + col;
                split1(c[0] + bb0, h0, l0); split1(c[1] + bb1, h1, l1);
                *(__half2*)&Chi[o] = __halves2half2(h0, h1);
                *(__half2*)&Clo[o] = __halves2half2(l0, l1);
                split1(c[2] + bb0, h0, l0); split1(c[3] + bb1, h1, l1);
                o += 8 * (size_t)ldc;
                *(__half2*)&Chi[o] = __halves2half2(h0, h1);
                *(__half2*)&Clo[o] = __halves2half2(l0, l1);
            }
        }
    }
}

// ---------------- elementwise ----------------
__global__ void split_f(const float* __restrict__ in, __half* __restrict__ hi, __half* __restrict__ lo) {
    size_t i = (size_t)blockIdx.x * blockDim.x + threadIdx.x;
    float4 v = ((const float4*)in)[i];
    __half h0, h1, h2, h3, l0, l1, l2, l3;
    split1(v.x, h0, l0); split1(v.y, h1, l1); split1(v.z, h2, l2); split1(v.w, h3, l3);
    ((__half2*)hi)[2 * i]     = __halves2half2(h0, h1);
    ((__half2*)hi)[2 * i + 1] = __halves2half2(h2, h3);
    ((__half2*)lo)[2 * i]     = __halves2half2(l0, l1);
    ((__half2*)lo)[2 * i + 1] = __halves2half2(l2, l3);
}

// split all three weights in one launch; blockIdx.y selects W
__global__ void split_w3(const float* __restrict__ w0, const float* __restrict__ w1,
                         const float* __restrict__ w2, __half* __restrict__ wout) {
    const int sel = blockIdx.y;
    const float* in = (sel == 0) ? w0 : ((sel == 1) ? w1 : w2);
    __half* hi = wout + (size_t)(2 * sel) * Hh * Hh;
    __half* lo = hi + (size_t)Hh * Hh;
    size_t i = (size_t)blockIdx.x * blockDim.x + threadIdx.x;
    float4 v = ((const float4*)in)[i];
    __half h0, h1, h2, h3, l0, l1, l2, l3;
    split1(v.x, h0, l0); split1(v.y, h1, l1); split1(v.z, h2, l2); split1(v.w, h3, l3);
    ((__half2*)hi)[2 * i]     = __halves2half2(h0, h1);
    ((__half2*)hi)[2 * i + 1] = __halves2half2(h2, h3);
    ((__half2*)lo)[2 * i]     = __halves2half2(l0, l1);
    ((__half2*)lo)[2 * i + 1] = __halves2half2(l2, l3);
}

__global__ void softmax_split(const float* __restrict__ e, __half* __restrict__ phi, __half* __restrict__ plo) {
    const size_t row = blockIdx.x;
    const float4* p = (const float4*)(e + row * Ss);
    const int t = threadIdx.x;
    float4 v[4];
    float mx = -1e30f;
#pragma unroll
    for (int c = 0; c < 4; c++) {
        v[c] = p[t + c * 256];
        mx = fmaxf(mx, fmaxf(fmaxf(v[c].x, v[c].y), fmaxf(v[c].z, v[c].w)));
    }
    __shared__ float red[256];
    red[t] = mx; __syncthreads();
    for (int s = 128; s > 0; s >>= 1) { if (t < s) red[t] = fmaxf(red[t], red[t + s]); __syncthreads(); }
    mx = red[0]; __syncthreads();
    float sum = 0.0f;
#pragma unroll
    for (int c = 0; c < 4; c++) {
        v[c].x = __expf(v[c].x - mx); v[c].y = __expf(v[c].y - mx);
        v[c].z = __expf(v[c].z - mx); v[c].w = __expf(v[c].w - mx);
        sum += v[c].x + v[c].y + v[c].z + v[c].w;
    }
    red[t] = sum; __syncthreads();
    for (int s = 128; s > 0; s >>= 1) { if (t < s) red[t] += red[t + s]; __syncthreads(); }
    const float inv = 1.0f / red[0];
    __half2* ph = (__half2*)(phi + row * Ss);
    __half2* pl = (__half2*)(plo + row * Ss);
#pragma unroll
    for (int c = 0; c < 4; c++) {
        __half h0, h1, h2, h3, l0, l1, l2, l3;
        split1(v[c].x * inv, h0, l0); split1(v[c].y * inv, h1, l1);
        split1(v[c].z * inv, h2, l2); split1(v[c].w * inv, h3, l3);
        int idx = t + c * 256;
        ph[2 * idx] = __halves2half2(h0, h1); ph[2 * idx + 1] = __halves2half2(h2, h3);
        pl[2 * idx] = __halves2half2(l0, l1); pl[2 * idx + 1] = __halves2half2(l2, l3);
    }
}

// ---------------- host ----------------
extern "C" void kernel_launch(void* const* d_in, const int* in_sizes, int n_in,
                              void* d_out, int out_size)
{
    const float* x  = (const float*)d_in[0];
    const float* Wq = (const float*)d_in[1];
    const float* bq = (const float*)d_in[2];
    const float* Wk = (const float*)d_in[3];
    const float* bk = (const float*)d_in[4];
    const float* Wv = (const float*)d_in[5];
    const float* bv = (const float*)d_in[6];
    float* out = (float*)d_out;

    __half *xhi, *xlo, *w, *qkvhi, *qkvlo, *phi, *plo;
    float* e;
    cudaGetSymbolAddress((void**)&xhi, g_xhi);
    cudaGetSymbolAddress((void**)&xlo, g_xlo);
    cudaGetSymbolAddress((void**)&w,   g_w);
    cudaGetSymbolAddress((void**)&qkvhi, g_qkvhi);
    cudaGetSymbolAddress((void**)&qkvlo, g_qkvlo);
    cudaGetSymbolAddress((void**)&e,   g_e);
    cudaGetSymbolAddress((void**)&phi, g_phi);
    cudaGetSymbolAddress((void**)&plo, g_plo);

    cudaFuncSetAttribute(gemm_mma<1, 1>, cudaFuncAttributeMaxDynamicSharedMemorySize, SMEMB);
    cudaFuncSetAttribute(gemm_mma<0, 0>, cudaFuncAttributeMaxDynamicSharedMemorySize, SMEMB);
    cudaFuncSetAttribute(gemm_mma<1, 0>, cudaFuncAttributeMaxDynamicSharedMemorySize, SMEMB);

    const size_t HH = (size_t)Hh * Hh;
    const size_t QKV = (size_t)MT * Hh;

    split_f<<<(size_t)MT * Hh / 1024, 256>>>(x, xhi, xlo);
    split_w3<<<dim3(HH / 1024, 3), 256>>>(Wq, Wk, Wv, w);

    // merged projections: z in {0,1,2} -> q,k,v = x @ W_z + b_z (fp16 hi/lo out)
    gemm_mma<1, 1><<<dim3(8, 128, 3), 256, SMEMB>>>(
        xhi, xlo, Hh, 0,
        w, w + HH, Hh, (ll)(2 * HH),
        bq, bk, bv, 1.0f,
        nullptr, qkvhi, qkvlo, Hh, (ll)QKV, Hh);

    // energy = Q @ K^T / 32 (B NT), fp32 out, per-batch
    gemm_mma<0, 0><<<dim3(32, 32, 4), 256, SMEMB>>>(
        qkvhi, qkvlo, Hh, (ll)Ss * Hh,
        qkvhi + QKV, qkvlo + QKV, Hh, (ll)Ss * Hh,
        nullptr, nullptr, nullptr, 1.0f / 32.0f,
        e, nullptr, nullptr, Ss, (ll)Ss * Ss, Hh);

    softmax_split<<<MT, 256>>>(e, phi, plo);

    // out = P @ V (B NN), fp32 out, per-batch
    gemm_mma<1, 0><<<dim3(8, 32, 4), 256, SMEMB>>>(
        phi, plo, Ss, (ll)Ss * Ss,
        qkvhi + 2 * QKV, qkvlo + 2 * QKV, Hh, (ll)Ss * Hh,
        nullptr, nullptr, nullptr, 1.0f,
        out, nullptr, nullptr, Hh, (ll)Ss * Hh, Ss);
}

// round 7
// speedup vs baseline: 2.7980x; 1.0509x over previous
#include <cuda_runtime.h>
#include <cuda_fp16.h>
#include <cstdint>

typedef unsigned int u32;
typedef long long ll;

#define Ss 4096
#define Hh 1024
#define MT (4 * Ss)

// ---------------- scratch ----------------
__device__ __align__(256) __half g_xhi[(size_t)MT * Hh];
__device__ __align__(256) __half g_xlo[(size_t)MT * Hh];
__device__ __align__(256) __half g_w[6][(size_t)Hh * Hh];
__device__ __align__(256) __half g_qkvhi[3][(size_t)MT * Hh];
__device__ __align__(256) __half g_qkvlo[3][(size_t)MT * Hh];
__device__ __align__(256) float  g_e[(size_t)4 * Ss * Ss];
__device__ __align__(256) __half g_phi[(size_t)4 * Ss * Ss];
__device__ __align__(256) __half g_plo[(size_t)4 * Ss * Ss];

// ---------------- helpers ----------------
__device__ __forceinline__ u32 s2u(const void* p) {
    u32 a;
    asm("{ .reg .u64 t; cvta.to.shared.u64 t, %1; cvt.u32.u64 %0, t; }" : "=r"(a) : "l"(p));
    return a;
}
__device__ __forceinline__ void cp16(u32 dst, const void* src) {
    asm volatile("cp.async.cg.shared.global [%0], [%1], 16;" :: "r"(dst), "l"(src) : "memory");
}
#define CP_COMMIT() asm volatile("cp.async.commit_group;" ::: "memory")
#define CP_WAIT1()  asm volatile("cp.async.wait_group 1;" ::: "memory")
#define CP_WAIT0()  asm volatile("cp.async.wait_group 0;" ::: "memory")

#define LDSM4(R, addr) \
    asm volatile("ldmatrix.sync.aligned.m8n8.x4.shared.b16 {%0,%1,%2,%3}, [%4];" \
        : "=r"((R)[0]), "=r"((R)[1]), "=r"((R)[2]), "=r"((R)[3]) : "r"(addr))
#define LDSM4T(R, addr) \
    asm volatile("ldmatrix.sync.aligned.m8n8.x4.trans.shared.b16 {%0,%1,%2,%3}, [%4];" \
        : "=r"((R)[0]), "=r"((R)[1]), "=r"((R)[2]), "=r"((R)[3]) : "r"(addr))

#define MMA_(d, a, b) \
    asm volatile("mma.sync.aligned.m16n8k16.row.col.f32.f16.f16.f32 " \
        "{%0,%1,%2,%3},{%4,%5,%6,%7},{%8,%9},{%0,%1,%2,%3};" \
        : "+f"((d)[0]), "+f"((d)[1]), "+f"((d)[2]), "+f"((d)[3]) \
        : "r"((a)[0]), "r"((a)[1]), "r"((a)[2]), "r"((a)[3]), "r"((b)[0]), "r"((b)[1]))

__device__ __forceinline__ void split1(float v, __half& h, __half& l) {
    h = __float2half_rn(v);
    l = __float2half_rn(v - __half2float(h));
}

// ---------------- SMEM layout: K-chunk 32, 3 stages, 2 CTAs/SM ----------------
// NT operand: logical [128][32] halves stored paired: addr(r,k) = (r>>1)*144 + (r&1)*64 + k*2
//   -> 64 physical rows x 144B, 9216 B. cp.async phases write one 128B row: conflict-free.
// NN operand: [32][128] halves, pitch 136 halves (272B), 8704 B (fits 9216 slot).
#define OPB  9216
#define STGB (4 * OPB)
#define SMEMB (3 * STGB)

__device__ __forceinline__ void ld_nt(u32 dst, const __half* g, int ld, int r0, int k0, int tid) {
#pragma unroll
    for (int i = 0; i < 2; i++) {
        int q = tid + (i << 8);
        int r = q >> 2, c = q & 3;                 // logical row, quad-in-row
        u32 off = (u32)((r >> 1) * 144 + (r & 1) * 64 + c * 16);
        cp16(dst + off, g + (size_t)(r0 + r) * ld + k0 + c * 8);
    }
}
__device__ __forceinline__ void ld_nn(u32 dst, const __half* g, int ld, int n0, int k0, int tid) {
#pragma unroll
    for (int i = 0; i < 2; i++) {
        int q = tid + (i << 8);
        int r = q >> 4, c = q & 15;
        cp16(dst + (u32)(r * 272 + c * 16), g + (size_t)(k0 + r) * ld + n0 + c * 8);
    }
}

// NT paired-row ldmatrix address for logical (row R, col kcol)
__device__ __forceinline__ u32 nt_addr(int R, int kcol) {
    return (u32)((R >> 1) * 144 + (R & 1) * 64 + kcol * 2);
}

// -------- HMMA GEMM: C = scale*(A @ op(B)) [+ bias], fp16x3 fp32 emulation --------
template <int BNN, int OUTM>
__global__ __launch_bounds__(256, 2)
void gemm_mma(const __half* __restrict__ Ah, const __half* __restrict__ Al, int lda, ll sA,
              const __half* __restrict__ Bh, const __half* __restrict__ Bl, int ldb, ll sB,
              const float* __restrict__ b0, const float* __restrict__ b1,
              const float* __restrict__ b2, float scale,
              float* __restrict__ Cf, __half* __restrict__ Chi, __half* __restrict__ Clo,
              int ldc, ll sC, int K)
{
    extern __shared__ __align__(16) char smc[];
    const u32 sb = s2u(smc);
    const int tid = threadIdx.x, wid = tid >> 5, lid = tid & 31;
    const int wm = wid >> 1, wn = wid & 1;
    const int m0 = blockIdx.y * 128, n0 = blockIdx.x * 128, z = blockIdx.z;

    const __half* pAh = Ah + (ll)z * sA;
    const __half* pAl = Al + (ll)z * sA;
    const __half* pBh = Bh + (ll)z * sB;
    const __half* pBl = Bl + (ll)z * sB;
    const float* bias = (z == 0) ? b0 : ((z == 1) ? b1 : b2);

    float acc[64];
#pragma unroll
    for (int i = 0; i < 64; i++) acc[i] = 0.0f;

    const int nc = K >> 5;

    const int aRow = wm * 32 + (lid & 15);
    const int aColS = (lid >> 4) << 3;
    int bRow, bColS;
    if (BNN) { bRow = (lid & 7) + (((lid >> 3) & 1) << 3); bColS = wn * 64 + ((lid >> 4) << 3); }
    else     { bRow = wn * 64 + (lid & 7) + ((lid >> 4) << 3); bColS = ((lid >> 3) & 1) << 3; }

    // prologue: stages 0,1 <- chunks 0,1
#pragma unroll
    for (int j = 0; j < 2; j++) {
        u32 bs = sb + (u32)j * STGB;
        int k0 = j << 5;
        ld_nt(bs, pAh, lda, m0, k0, tid);
        ld_nt(bs + OPB, pAl, lda, m0, k0, tid);
        if (BNN) { ld_nn(bs + 2 * OPB, pBh, ldb, n0, k0, tid); ld_nn(bs + 3 * OPB, pBl, ldb, n0, k0, tid); }
        else     { ld_nt(bs + 2 * OPB, pBh, ldb, n0, k0, tid); ld_nt(bs + 3 * OPB, pBl, ldb, n0, k0, tid); }
        CP_COMMIT();
    }

    int stg = 0;
    for (int j = 0; j < nc; j++) {
        if (j + 2 < nc) CP_WAIT1(); else CP_WAIT0();
        __syncthreads();
        if (j + 2 < nc) {
            int s2 = (j + 2) % 3;
            u32 bs = sb + (u32)s2 * STGB;
            int k0 = (j + 2) << 5;
            ld_nt(bs, pAh, lda, m0, k0, tid);
            ld_nt(bs + OPB, pAl, lda, m0, k0, tid);
            if (BNN) { ld_nn(bs + 2 * OPB, pBh, ldb, n0, k0, tid); ld_nn(bs + 3 * OPB, pBl, ldb, n0, k0, tid); }
            else     { ld_nt(bs + 2 * OPB, pBh, ldb, n0, k0, tid); ld_nt(bs + 3 * OPB, pBl, ldb, n0, k0, tid); }
            CP_COMMIT();
        }
        const u32 sS = sb + (u32)stg * STGB;
        const u32 sAh = sS, sAl = sS + OPB, sBh = sS + 2 * OPB, sBl = sS + 3 * OPB;

#pragma unroll
        for (int kk = 0; kk < 2; kk++) {
            const int kb = kk << 4;
            u32 ah[8], al[8], bb[16];
            // A fragments (hi+lo)
#pragma unroll
            for (int mi = 0; mi < 2; mi++) {
                u32 off = nt_addr(aRow + mi * 16, kb + aColS);
                LDSM4(ah + mi * 4, sAh + off);
                LDSM4(al + mi * 4, sAl + off);
            }
            // B hi fragments
#pragma unroll
            for (int p4 = 0; p4 < 4; p4++) {
                if (BNN) LDSM4T(bb + p4 * 4, sBh + (u32)(((kb + bRow) * 136 + bColS + p4 * 16) * 2));
                else     LDSM4(bb + p4 * 4, sBh + nt_addr(bRow + p4 * 16, kb + bColS));
            }
            // Ah*Bh, Al*Bh
#pragma unroll
            for (int mi = 0; mi < 2; mi++)
#pragma unroll
                for (int nj = 0; nj < 8; nj++) MMA_(acc + (mi * 8 + nj) * 4, ah + mi * 4, bb + nj * 2);
#pragma unroll
            for (int mi = 0; mi < 2; mi++)
#pragma unroll
                for (int nj = 0; nj < 8; nj++) MMA_(acc + (mi * 8 + nj) * 4, al + mi * 4, bb + nj * 2);
            // B lo fragments (reuse bb)
#pragma unroll
            for (int p4 = 0; p4 < 4; p4++) {
                if (BNN) LDSM4T(bb + p4 * 4, sBl + (u32)(((kb + bRow) * 136 + bColS + p4 * 16) * 2));
                else     LDSM4(bb + p4 * 4, sBl + nt_addr(bRow + p4 * 16, kb + bColS));
            }
            // Ah*Bl
#pragma unroll
            for (int mi = 0; mi < 2; mi++)
#pragma unroll
                for (int nj = 0; nj < 8; nj++) MMA_(acc + (mi * 8 + nj) * 4, ah + mi * 4, bb + nj * 2);
        }
        stg = (stg + 1) % 3;
    }

    // -------- epilogue --------
    const int g = lid >> 2, t4 = lid & 3;
#pragma unroll
    for (int mi = 0; mi < 2; mi++) {
#pragma unroll
        for (int nj = 0; nj < 8; nj++) {
            const float* c = acc + (mi * 8 + nj) * 4;
            int row = m0 + wm * 32 + mi * 16 + g;
            int col = n0 + wn * 64 + nj * 8 + t4 * 2;
            if (OUTM == 0) {
                size_t base = (size_t)((ll)z * sC) + (size_t)row * ldc + col;
                *(float2*)&Cf[base] = make_float2(c[0] * scale, c[1] * scale);
                *(float2*)&Cf[base + 8 * (size_t)ldc] = make_float2(c[2] * scale, c[3] * scale);
            } else {
                float bb0 = bias[col], bb1 = bias[col + 1];
                __half h0, h1, l0, l1;
                size_t o = (size_t)((ll)z * sC) + (size_t)row * ldc + col;
                split1(c[0] + bb0, h0, l0); split1(c[1] + bb1, h1, l1);
                *(__half2*)&Chi[o] = __halves2half2(h0, h1);
                *(__half2*)&Clo[o] = __halves2half2(l0, l1);
                split1(c[2] + bb0, h0, l0); split1(c[3] + bb1, h1, l1);
                o += 8 * (size_t)ldc;
                *(__half2*)&Chi[o] = __halves2half2(h0, h1);
                *(__half2*)&Clo[o] = __halves2half2(l0, l1);
            }
        }
    }
}

// ---------------- elementwise ----------------
__global__ void split_f(const float* __restrict__ in, __half* __restrict__ hi, __half* __restrict__ lo) {
    size_t i = (size_t)blockIdx.x * blockDim.x + threadIdx.x;
    float4 v = ((const float4*)in)[i];
    __half h0, h1, h2, h3, l0, l1, l2, l3;
    split1(v.x, h0, l0); split1(v.y, h1, l1); split1(v.z, h2, l2); split1(v.w, h3, l3);
    ((__half2*)hi)[2 * i]     = __halves2half2(h0, h1);
    ((__half2*)hi)[2 * i + 1] = __halves2half2(h2, h3);
    ((__half2*)lo)[2 * i]     = __halves2half2(l0, l1);
    ((__half2*)lo)[2 * i + 1] = __halves2half2(l2, l3);
}

__global__ void split_w3(const float* __restrict__ w0, const float* __restrict__ w1,
                         const float* __restrict__ w2, __half* __restrict__ wout) {
    const int sel = blockIdx.y;
    const float* in = (sel == 0) ? w0 : ((sel == 1) ? w1 : w2);
    __half* hi = wout + (size_t)(2 * sel) * Hh * Hh;
    __half* lo = hi + (size_t)Hh * Hh;
    size_t i = (size_t)blockIdx.x * blockDim.x + threadIdx.x;
    float4 v = ((const float4*)in)[i];
    __half h0, h1, h2, h3, l0, l1, l2, l3;
    split1(v.x, h0, l0); split1(v.y, h1, l1); split1(v.z, h2, l2); split1(v.w, h3, l3);
    ((__half2*)hi)[2 * i]     = __halves2half2(h0, h1);
    ((__half2*)hi)[2 * i + 1] = __halves2half2(h2, h3);
    ((__half2*)lo)[2 * i]     = __halves2half2(l0, l1);
    ((__half2*)lo)[2 * i + 1] = __halves2half2(l2, l3);
}

__global__ void softmax_split(const float* __restrict__ e, __half* __restrict__ phi, __half* __restrict__ plo) {
    const size_t row = blockIdx.x;
    const float4* p = (const float4*)(e + row * Ss);
    const int t = threadIdx.x;
    float4 v[4];
    float mx = -1e30f;
#pragma unroll
    for (int c = 0; c < 4; c++) {
        v[c] = p[t + c * 256];
        mx = fmaxf(mx, fmaxf(fmaxf(v[c].x, v[c].y), fmaxf(v[c].z, v[c].w)));
    }
    __shared__ float red[256];
    red[t] = mx; __syncthreads();
    for (int s = 128; s > 0; s >>= 1) { if (t < s) red[t] = fmaxf(red[t], red[t + s]); __syncthreads(); }
    mx = red[0]; __syncthreads();
    float sum = 0.0f;
#pragma unroll
    for (int c = 0; c < 4; c++) {
        v[c].x = __expf(v[c].x - mx); v[c].y = __expf(v[c].y - mx);
        v[c].z = __expf(v[c].z - mx); v[c].w = __expf(v[c].w - mx);
        sum += v[c].x + v[c].y + v[c].z + v[c].w;
    }
    red[t] = sum; __syncthreads();
    for (int s = 128; s > 0; s >>= 1) { if (t < s) red[t] += red[t + s]; __syncthreads(); }
    const float inv = 1.0f / red[0];
    __half2* ph = (__half2*)(phi + row * Ss);
    __half2* pl = (__half2*)(plo + row * Ss);
#pragma unroll
    for (int c = 0; c < 4; c++) {
        __half h0, h1, h2, h3, l0, l1, l2, l3;
        split1(v[c].x * inv, h0, l0); split1(v[c].y * inv, h1, l1);
        split1(v[c].z * inv, h2, l2); split1(v[c].w * inv, h3, l3);
        int idx = t + c * 256;
        ph[2 * idx] = __halves2half2(h0, h1); ph[2 * idx + 1] = __halves2half2(h2, h3);
        pl[2 * idx] = __halves2half2(l0, l1); pl[2 * idx + 1] = __halves2half2(l2, l3);
    }
}

// ---------------- host ----------------
extern "C" void kernel_launch(void* const* d_in, const int* in_sizes, int n_in,
                              void* d_out, int out_size)
{
    const float* x  = (const float*)d_in[0];
    const float* Wq = (const float*)d_in[1];
    const float* bq = (const float*)d_in[2];
    const float* Wk = (const float*)d_in[3];
    const float* bk = (const float*)d_in[4];
    const float* Wv = (const float*)d_in[5];
    const float* bv = (const float*)d_in[6];
    float* out = (float*)d_out;

    __half *xhi, *xlo, *w, *qkvhi, *qkvlo, *phi, *plo;
    float* e;
    cudaGetSymbolAddress((void**)&xhi, g_xhi);
    cudaGetSymbolAddress((void**)&xlo, g_xlo);
    cudaGetSymbolAddress((void**)&w,   g_w);
    cudaGetSymbolAddress((void**)&qkvhi, g_qkvhi);
    cudaGetSymbolAddress((void**)&qkvlo, g_qkvlo);
    cudaGetSymbolAddress((void**)&e,   g_e);
    cudaGetSymbolAddress((void**)&phi, g_phi);
    cudaGetSymbolAddress((void**)&plo, g_plo);

    cudaFuncSetAttribute(gemm_mma<1, 1>, cudaFuncAttributeMaxDynamicSharedMemorySize, SMEMB);
    cudaFuncSetAttribute(gemm_mma<0, 0>, cudaFuncAttributeMaxDynamicSharedMemorySize, SMEMB);
    cudaFuncSetAttribute(gemm_mma<1, 0>, cudaFuncAttributeMaxDynamicSharedMemorySize, SMEMB);

    const size_t HH = (size_t)Hh * Hh;
    const size_t QKV = (size_t)MT * Hh;

    split_f<<<(size_t)MT * Hh / 1024, 256>>>(x, xhi, xlo);
    split_w3<<<dim3(HH / 1024, 3), 256>>>(Wq, Wk, Wv, w);

    // merged projections: z in {0,1,2} -> q,k,v = x @ W_z + b_z (fp16 hi/lo out)
    gemm_mma<1, 1><<<dim3(8, 128, 3), 256, SMEMB>>>(
        xhi, xlo, Hh, 0,
        w, w + HH, Hh, (ll)(2 * HH),
        bq, bk, bv, 1.0f,
        nullptr, qkvhi, qkvlo, Hh, (ll)QKV, Hh);

    // energy = Q @ K^T / 32 (B NT), fp32 out, per-batch
    gemm_mma<0, 0><<<dim3(32, 32, 4), 256, SMEMB>>>(
        qkvhi, qkvlo, Hh, (ll)Ss * Hh,
        qkvhi + QKV, qkvlo + QKV, Hh, (ll)Ss * Hh,
        nullptr, nullptr, nullptr, 1.0f / 32.0f,
        e, nullptr, nullptr, Ss, (ll)Ss * Ss, Hh);

    softmax_split<<<MT, 256>>>(e, phi, plo);

    // out = P @ V (B NN), fp32 out, per-batch
    gemm_mma<1, 0><<<dim3(8, 32, 4), 256, SMEMB>>>(
        phi, plo, Ss, (ll)Ss * Ss,
        qkvhi + 2 * QKV, qkvlo + 2 * QKV, Hh, (ll)Ss * Hh,
        nullptr, nullptr, nullptr, 1.0f,
        out, nullptr, nullptr, Hh, (ll)Ss * Hh, Ss);
}